// round 1
// baseline (speedup 1.0000x reference)
#include <cuda_runtime.h>
#include <cstdint>

// ---------------------------------------------------------------------------
// CapsuleLayer fused dynamic routing, fp32.
//   inputs [64,2048,16], W [1,2048,32,16,16] -> out [64,32,16]
// Routing coefficients c2 are a pure per-(b,n) function of h = sum_d ih, so the
// whole 3-iteration loop fuses into a single streaming pass over W.
// ---------------------------------------------------------------------------

#define BATCH   64
#define NI      2048
#define DI      16
#define NO      32
#define DOUT    16

#define NCHUNK  16                  // n's per block
#define BCHUNK  16                  // b's per block
#define NG      (NI / NCHUNK)       // 128
#define BG      (BATCH / BCHUNK)    // 4
#define THREADS (NO * BCHUNK)       // 512

#define XS_BSTRIDE 20                       // pad 16 -> 20 floats (2-phase LDS.128)
#define XS_NSTRIDE (BCHUNK * XS_BSTRIDE)    // 320
#define W_OSTRIDE  260                      // pad 256 -> 260 (1-phase LDS.128, 16B aligned)
#define WSM_FLOATS (NO * W_OSTRIDE)         // 8320
#define HPAD       33

#define SMEM_FLOATS (NCHUNK * XS_NSTRIDE + 2 * WSM_FLOATS + 2 * BCHUNK * HPAD)
#define SMEM_BYTES  (SMEM_FLOATS * 4)       // 91264 B

// Deterministic partial accumulators: [ng][o*16+dd][b]  (b contiguous -> coalesced)
__device__ float g_part[(size_t)NG * 512 * BATCH];   // 16 MB

__device__ __forceinline__ unsigned smem_u32(const void* p) {
    return (unsigned)__cvta_generic_to_shared(p);
}
__device__ __forceinline__ void cp16(unsigned dst, const void* src) {
    asm volatile("cp.async.cg.shared.global [%0], [%1], 16;\n" :: "r"(dst), "l"(src));
}
__device__ __forceinline__ void cp_commit() {
    asm volatile("cp.async.commit_group;\n" ::: "memory");
}

__device__ __forceinline__ void load_W_async(float* wbuf, const float* Wn, int t) {
    // 32 o-rows x 256 floats, row -> wbuf[o*260 .. +255], 16B chunks, coalesced
#pragma unroll
    for (int k = 0; k < 4; k++) {
        int c  = t + k * THREADS;       // 0..2047
        int oc = c >> 6;                // row
        int j4 = (c & 63) << 2;         // float offset within row (mult of 4)
        cp16(smem_u32(wbuf + oc * W_OSTRIDE + j4), Wn + oc * 256 + j4);
    }
}

__global__ void __launch_bounds__(THREADS, 1)
caps_main(const float* __restrict__ inp, const float* __restrict__ Wg) {
    extern __shared__ float smem[];
    float* xs    = smem;                               // NCHUNK*320
    float* Wsm   = xs + NCHUNK * XS_NSTRIDE;           // 2 * 8320
    float* h_sm  = Wsm + 2 * WSM_FLOATS;               // 16*33
    float* c2_sm = h_sm + BCHUNK * HPAD;               // 16*33

    const int t    = threadIdx.x;
    const int o    = t >> 4;          // 0..31
    const int bb   = t & 15;          // 0..15
    const int bg   = blockIdx.x;      // 0..3
    const int ng   = blockIdx.y;      // 0..127
    const int n0   = ng * NCHUNK;
    const int wid  = t >> 5;          // routing: warp wid handles b = wid
    const int lane = t & 31;          // routing: lane = o

    // -------- prologue: async-load all x for this (bg, ng) tile + W[n0] -----
#pragma unroll
    for (int k = 0; k < 2; k++) {     // 1024 chunks of 16B
        int c   = t + k * THREADS;
        int e4  = c * 4;              // flat float idx: bbv*256 + nn*16 + i
        int bbv = e4 >> 8;
        int rem = e4 & 255;           // nn*16 + i
        int nn  = rem >> 4;
        int i   = rem & 15;
        const float* src = inp + (size_t)(bg * BCHUNK + bbv) * (NI * DI) + n0 * DI + rem;
        cp16(smem_u32(xs + nn * XS_NSTRIDE + bbv * XS_BSTRIDE + i), src);
    }
    load_W_async(Wsm, Wg + (size_t)n0 * (NO * DOUT * DI), t);
    cp_commit();

    float acc[DOUT];
#pragma unroll
    for (int d = 0; d < DOUT; d++) acc[d] = 0.f;

    for (int nn = 0; nn < NCHUNK; nn++) {
        float* wbuf = Wsm + (nn & 1) * WSM_FLOATS;
        if (nn + 1 < NCHUNK) {
            load_W_async(Wsm + ((nn + 1) & 1) * WSM_FLOATS,
                         Wg + (size_t)(n0 + nn + 1) * (NO * DOUT * DI), t);
            cp_commit();
            asm volatile("cp.async.wait_group 1;\n" ::: "memory");
        } else {
            asm volatile("cp.async.wait_group 0;\n" ::: "memory");
        }
        __syncthreads();

        // ---- x into registers (broadcast-friendly) ----
        const float* xp = xs + nn * XS_NSTRIDE + bb * XS_BSTRIDE;
        const float4 X0 = *(const float4*)(xp + 0);
        const float4 X1 = *(const float4*)(xp + 4);
        const float4 X2 = *(const float4*)(xp + 8);
        const float4 X3 = *(const float4*)(xp + 12);

        // ---- ih[dd] = W[n,o,dd,:] . x   ;  h = sum_dd ih ----
        const float* wrow = wbuf + o * W_OSTRIDE;
        float ih[DOUT];
        float h = 0.f;
#pragma unroll
        for (int dd = 0; dd < DOUT; dd++) {
            const float4 w0 = *(const float4*)(wrow + dd * 16 + 0);
            const float4 w1 = *(const float4*)(wrow + dd * 16 + 4);
            const float4 w2 = *(const float4*)(wrow + dd * 16 + 8);
            const float4 w3 = *(const float4*)(wrow + dd * 16 + 12);
            float v = w0.x * X0.x;
            v = fmaf(w0.y, X0.y, v); v = fmaf(w0.z, X0.z, v); v = fmaf(w0.w, X0.w, v);
            v = fmaf(w1.x, X1.x, v); v = fmaf(w1.y, X1.y, v);
            v = fmaf(w1.z, X1.z, v); v = fmaf(w1.w, X1.w, v);
            v = fmaf(w2.x, X2.x, v); v = fmaf(w2.y, X2.y, v);
            v = fmaf(w2.z, X2.z, v); v = fmaf(w2.w, X2.w, v);
            v = fmaf(w3.x, X3.x, v); v = fmaf(w3.y, X3.y, v);
            v = fmaf(w3.z, X3.z, v); v = fmaf(w3.w, X3.w, v);
            ih[dd] = v;
            h += v;
        }
        h_sm[bb * HPAD + o] = h;
        __syncthreads();

        // ---- routing: warp `wid` does the 32-wide softmax chain for b=wid ----
        {
            float hv = h_sm[wid * HPAD + lane];
            float b1 = hv * 0.03125f;                 // b after iter 0: h/32
            float m = b1;
#pragma unroll
            for (int s = 16; s > 0; s >>= 1) m = fmaxf(m, __shfl_xor_sync(0xffffffffu, m, s));
            float e = __expf(b1 - m);
            float sum = e;
#pragma unroll
            for (int s = 16; s > 0; s >>= 1) sum += __shfl_xor_sync(0xffffffffu, sum, s);
            float c1 = __fdividef(e, sum);
            float b2 = fmaf(c1, hv, b1);              // b after iter 1
            float m2 = b2;
#pragma unroll
            for (int s = 16; s > 0; s >>= 1) m2 = fmaxf(m2, __shfl_xor_sync(0xffffffffu, m2, s));
            float e2 = __expf(b2 - m2);
            float s2 = e2;
#pragma unroll
            for (int s = 16; s > 0; s >>= 1) s2 += __shfl_xor_sync(0xffffffffu, s2, s);
            c2_sm[wid * HPAD + lane] = __fdividef(e2, s2);
        }
        __syncthreads();

        const float c2v = c2_sm[bb * HPAD + o];
#pragma unroll
        for (int dd = 0; dd < DOUT; dd++) acc[dd] = fmaf(c2v, ih[dd], acc[dd]);
    }

    // -------- epilogue: partials [ng][o*16+dd][b], b contiguous ------------
    float* pp = g_part + (size_t)ng * (512 * BATCH) + (bg * BCHUNK + bb);
#pragma unroll
    for (int dd = 0; dd < DOUT; dd++)
        pp[(o * 16 + dd) * BATCH] = acc[dd];
}

// grid = 32 (one per o), 1024 threads: t -> (dd = t>>6, b = t&63)
__global__ void __launch_bounds__(1024, 1)
caps_finalize(float* __restrict__ out) {
    __shared__ float red[16 * 64];
    const int t  = threadIdx.x;
    const int o  = blockIdx.x;
    const int dd = t >> 6;
    const int b  = t & 63;

    float s = 0.f;
    const float* p = g_part + (o * 16 + dd) * BATCH + b;
#pragma unroll 8
    for (int ng = 0; ng < NG; ng++) s += p[(size_t)ng * (512 * BATCH)];

    red[dd * 64 + b] = s * s;
    __syncthreads();
    float s2 = 0.f;
#pragma unroll
    for (int k = 0; k < 16; k++) s2 += red[k * 64 + b];

    const float scale = s2 / ((1.f + s2) * sqrtf(s2 + 1e-7f));
    out[b * 512 + o * 16 + dd] = scale * s;
}

extern "C" void kernel_launch(void* const* d_in, const int* in_sizes, int n_in,
                              void* d_out, int out_size) {
    const float* inp;
    const float* Wg;
    if (in_sizes[0] == BATCH * NI * DI) {      // 2,097,152
        inp = (const float*)d_in[0];
        Wg  = (const float*)d_in[1];
    } else {                                   // defensive: order swapped
        inp = (const float*)d_in[1];
        Wg  = (const float*)d_in[0];
    }

    cudaFuncSetAttribute(caps_main, cudaFuncAttributeMaxDynamicSharedMemorySize, SMEM_BYTES);

    dim3 grid(BG, NG);   // x = bgroup (4), y = ngroup (128): same-n blocks wave-adjacent -> W hits L2
    caps_main<<<grid, THREADS, SMEM_BYTES>>>(inp, Wg);
    caps_finalize<<<NO, 1024>>>((float*)d_out);
}